// round 2
// baseline (speedup 1.0000x reference)
#include <cuda_runtime.h>
#include <math.h>
#include <stdint.h>

#define NN 12288
#define DD 128
#define KK 20
#define HID 128
#define OUTD 64
#define E_TOT (NN*(KK+1))

// ---------------- scratch (device globals; no allocations allowed) ----------------
// All referenced ONLY from device code (passing __device__ symbols as host-side
// kernel args is invalid and was the Round-1 crash).
__device__ float g_xn[NN*DD];                       // normalized x
__device__ float g_adj[(size_t)NN*(size_t)NN];      // 604 MB similarity matrix
__device__ float g_topv[NN*KK];
__device__ int   g_topi[NN*KK];
__device__ float g_deg[NN];
__device__ float g_dis[NN];
__device__ int   g_cnt[NN];
__device__ int   g_off[NN+1];
__device__ int   g_fill[NN];
__device__ int   g_esrc[E_TOT];
__device__ float g_ew[E_TOT];
__device__ float g_hw1[NN*HID];
__device__ float g_h[NN*HID];
__device__ float g_hw2[NN*OUTD];

// ---------------- 1. row-normalize x ----------------
__global__ void normalize_kernel(const float* __restrict__ x) {
    int warp = (blockIdx.x * blockDim.x + threadIdx.x) >> 5;
    int lane = threadIdx.x & 31;
    if (warp >= NN) return;
    const float4* xr = (const float4*)(x + (size_t)warp * DD);
    float4 v = xr[lane];
    float ss = v.x*v.x + v.y*v.y + v.z*v.z + v.w*v.w;
    #pragma unroll
    for (int o = 16; o; o >>= 1) ss += __shfl_xor_sync(0xffffffffu, ss, o);
    float inv = 1.0f / fmaxf(sqrtf(ss), 1e-12f);
    float4 o4 = make_float4(v.x*inv, v.y*inv, v.z*inv, v.w*inv);
    ((float4*)(g_xn + (size_t)warp*DD))[lane] = o4;
}

// ---------------- 2. adj = xn @ xn^T  (fp32 SIMT GEMM) ----------------
// 128x128 tile per 256-thread block, 8x8 per thread, K-chunk 32.
#define BK 32
#define PAD 133
__global__ void __launch_bounds__(256) adj_gemm_kernel() {
    __shared__ float As[BK][PAD];
    __shared__ float Bs[BK][PAD];
    int tid = threadIdx.x;
    int tx = tid & 15;
    int ty = tid >> 4;
    int rowBase = blockIdx.y * 128;
    int colBase = blockIdx.x * 128;

    float acc[8][8];
    #pragma unroll
    for (int i = 0; i < 8; i++)
        #pragma unroll
        for (int j = 0; j < 8; j++) acc[i][j] = 0.f;

    for (int k0 = 0; k0 < DD; k0 += BK) {
        #pragma unroll
        for (int it = 0; it < 4; it++) {
            int idx = tid + it * 256;       // 0..1023
            int r = idx >> 3;               // 0..127
            int q = idx & 7;                // float4 slot within 32-wide k chunk
            float4 va = *(const float4*)&g_xn[(size_t)(rowBase + r) * DD + k0 + q*4];
            As[q*4+0][r] = va.x; As[q*4+1][r] = va.y; As[q*4+2][r] = va.z; As[q*4+3][r] = va.w;
            float4 vb = *(const float4*)&g_xn[(size_t)(colBase + r) * DD + k0 + q*4];
            Bs[q*4+0][r] = vb.x; Bs[q*4+1][r] = vb.y; Bs[q*4+2][r] = vb.z; Bs[q*4+3][r] = vb.w;
        }
        __syncthreads();
        #pragma unroll 4
        for (int k = 0; k < BK; k++) {
            float a[8], b[8];
            #pragma unroll
            for (int i = 0; i < 4; i++) {
                a[i]   = As[k][ty*4 + i];
                a[4+i] = As[k][64 + ty*4 + i];
                b[i]   = Bs[k][tx*4 + i];
                b[4+i] = Bs[k][64 + tx*4 + i];
            }
            #pragma unroll
            for (int i = 0; i < 8; i++)
                #pragma unroll
                for (int j = 0; j < 8; j++)
                    acc[i][j] += a[i] * b[j];
        }
        __syncthreads();
    }

    #pragma unroll
    for (int ih = 0; ih < 2; ih++) {
        #pragma unroll
        for (int i = 0; i < 4; i++) {
            int row = rowBase + ih*64 + ty*4 + i;
            #pragma unroll
            for (int jh = 0; jh < 2; jh++) {
                float4 v = make_float4(acc[ih*4+i][jh*4+0], acc[ih*4+i][jh*4+1],
                                       acc[ih*4+i][jh*4+2], acc[ih*4+i][jh*4+3]);
                *(float4*)&g_adj[(size_t)row * NN + colBase + jh*64 + tx*4] = v;
            }
        }
    }
}

// ---------------- 3. per-row top-20 ----------------
__global__ void __launch_bounds__(128) topk_kernel() {
    int r = blockIdx.x;
    int tid = threadIdx.x;
    const float* row = g_adj + (size_t)r * NN;

    float lv[KK]; int li[KK];
    #pragma unroll
    for (int i = 0; i < KK; i++) { lv[i] = -2.f; li[i] = -1; }
    float vmin = -2.f; int pmin = 0;

    for (int c = tid; c < NN; c += 128) {
        float v = row[c];
        if (v > vmin) {
            lv[pmin] = v; li[pmin] = c;
            vmin = lv[0]; pmin = 0;
            #pragma unroll
            for (int i = 1; i < KK; i++)
                if (lv[i] < vmin) { vmin = lv[i]; pmin = i; }
        }
    }

    __shared__ float sv[128*KK];
    __shared__ int   si[128*KK];
    __shared__ float rmax[128];
    __shared__ int   rpos[128];
    #pragma unroll
    for (int i = 0; i < KK; i++) { sv[tid*KK + i] = lv[i]; si[tid*KK + i] = li[i]; }
    __syncthreads();

    for (int sel = 0; sel < KK; sel++) {
        float mv = -3.f; int mp = 0;
        for (int j = tid; j < 128*KK; j += 128)
            if (sv[j] > mv) { mv = sv[j]; mp = j; }
        rmax[tid] = mv; rpos[tid] = mp;
        __syncthreads();
        for (int d = 64; d > 0; d >>= 1) {
            if (tid < d && rmax[tid + d] > rmax[tid]) {
                rmax[tid] = rmax[tid + d]; rpos[tid] = rpos[tid + d];
            }
            __syncthreads();
        }
        if (tid == 0) {
            int p = rpos[0];
            g_topv[r*KK + sel] = sv[p];
            g_topi[r*KK + sel] = si[p];
            sv[p] = -3.f;
        }
        __syncthreads();
    }
}

// ---------------- 4. init counters (re-zeroed every launch for determinism) ----------------
__global__ void init_kernel() {
    int i = blockIdx.x * blockDim.x + threadIdx.x;
    if (i < NN) { g_deg[i] = 0.f; g_cnt[i] = 0; }
}

// ---------------- 5. degree + in-count ----------------
__global__ void deg_kernel() {
    int r = blockIdx.x * blockDim.x + threadIdx.x;
    if (r >= NN) return;
    bool self = false;
    #pragma unroll
    for (int k = 0; k < KK; k++) {
        int c = g_topi[r*KK + k];
        float w = g_topv[r*KK + k];
        if (c == r) self = true;
        atomicAdd(&g_deg[c], w);
        atomicAdd(&g_cnt[c], 1);
    }
    atomicAdd(&g_deg[r], self ? 0.f : 1.f);
    atomicAdd(&g_cnt[r], 1);
}

// ---------------- 6. exclusive scan of cnt -> off (single block) ----------------
__global__ void __launch_bounds__(1024) scan_kernel() {
    __shared__ int partial[1024];
    int t = threadIdx.x;
    int base = t * 12;
    int local[12];
    int s = 0;
    #pragma unroll
    for (int i = 0; i < 12; i++) { local[i] = s; s += g_cnt[base + i]; }
    partial[t] = s;
    __syncthreads();
    for (int d = 1; d < 1024; d <<= 1) {
        int v = (t >= d) ? partial[t - d] : 0;
        __syncthreads();
        partial[t] += v;
        __syncthreads();
    }
    int chunk_off = (t == 0) ? 0 : partial[t - 1];
    #pragma unroll
    for (int i = 0; i < 12; i++) {
        int o = chunk_off + local[i];
        g_off[base + i] = o;
        g_fill[base + i] = o;
    }
    if (t == 1023) g_off[NN] = partial[1023];
}

// ---------------- 7. dis = deg>0 ? rsqrt(max(deg,1e-30)) : 0 ----------------
__global__ void dis_kernel() {
    int i = blockIdx.x * blockDim.x + threadIdx.x;
    if (i >= NN) return;
    float d = g_deg[i];
    g_dis[i] = (d > 0.f) ? (1.0f / sqrtf(fmaxf(d, 1e-30f))) : 0.f;
}

// ---------------- 8. build transposed CSR with normalized weights ----------------
__global__ void fill_kernel() {
    int r = blockIdx.x * blockDim.x + threadIdx.x;
    if (r >= NN) return;
    float dr = g_dis[r];
    bool self = false;
    #pragma unroll
    for (int k = 0; k < KK; k++) {
        int c = g_topi[r*KK + k];
        float w = g_topv[r*KK + k];
        if (c == r) self = true;
        int p = atomicAdd(&g_fill[c], 1);
        g_esrc[p] = r;
        g_ew[p] = dr * w * g_dis[c];
    }
    float lw = self ? 0.f : 1.f;
    int p = atomicAdd(&g_fill[r], 1);
    g_esrc[p] = r;
    g_ew[p] = dr * dr * lw;
}

// ---------------- 9. dense Y = X @ W  (scratch selected by template inside) ----------------
template <int DOUT, bool FIRST>
__global__ void xw_kernel(const float* __restrict__ xin, const float* __restrict__ W) {
    const float* X = FIRST ? xin : (const float*)g_h;
    float* Y = FIRST ? g_hw1 : g_hw2;
    __shared__ float xs[16][DD];
    int j = threadIdx.x;           // output column
    int r0 = blockIdx.x * 16;
    for (int idx = j; idx < 16 * DD; idx += DOUT)
        xs[idx >> 7][idx & 127] = X[(size_t)(r0 + (idx >> 7)) * DD + (idx & 127)];
    __syncthreads();
    float acc[16];
    #pragma unroll
    for (int i = 0; i < 16; i++) acc[i] = 0.f;
    for (int k = 0; k < DD; k++) {
        float w = W[k * DOUT + j];
        #pragma unroll
        for (int i = 0; i < 16; i++) acc[i] += xs[i][k] * w;
    }
    #pragma unroll
    for (int i = 0; i < 16; i++) Y[(size_t)(r0 + i) * DOUT + j] = acc[i];
}

// ---------------- 10. aggregate over in-edges (+bias, optional relu) ----------------
template <int DH, bool RELU>
__global__ void agg_kernel(const float* __restrict__ b, float* __restrict__ outp) {
    const float* hw = RELU ? g_hw1 : g_hw2;
    float* dst = RELU ? g_h : outp;
    int c = blockIdx.x;
    int t = threadIdx.x;
    int e0 = g_off[c], e1 = g_off[c + 1];
    float acc = b[t];
    for (int e = e0; e < e1; e++) {
        int s = g_esrc[e];
        float w = g_ew[e];
        acc += w * hw[(size_t)s * DH + t];
    }
    if (RELU) acc = fmaxf(acc, 0.f);
    dst[(size_t)c * DH + t] = acc;
}

// ---------------- launch ----------------
extern "C" void kernel_launch(void* const* d_in, const int* in_sizes, int n_in,
                              void* d_out, int out_size) {
    const float* x  = (const float*)d_in[0];
    const float* W1 = (const float*)d_in[1];
    const float* b1 = (const float*)d_in[2];
    const float* W2 = (const float*)d_in[3];
    const float* b2 = (const float*)d_in[4];
    float* out = (float*)d_out;

    normalize_kernel<<<NN/8, 256>>>(x);
    adj_gemm_kernel<<<dim3(NN/128, NN/128), 256>>>();
    topk_kernel<<<NN, 128>>>();
    init_kernel<<<(NN + 255)/256, 256>>>();
    deg_kernel<<<(NN + 255)/256, 256>>>();
    scan_kernel<<<1, 1024>>>();
    dis_kernel<<<(NN + 255)/256, 256>>>();
    fill_kernel<<<(NN + 255)/256, 256>>>();

    xw_kernel<HID, true><<<NN/16, HID>>>(x, W1);
    agg_kernel<HID, true><<<NN, HID>>>(b1, nullptr);
    xw_kernel<OUTD, false><<<NN/16, OUTD>>>(nullptr, W2);
    agg_kernel<OUTD, false><<<NN, OUTD>>>(b2, out);
    (void)in_sizes; (void)n_in; (void)out_size;
}

// round 5
// speedup vs baseline: 1.0686x; 1.0686x over previous
#include <cuda_runtime.h>
#include <math.h>
#include <stdint.h>

#define NN 12288
#define DD 128
#define KK 20
#define HID 128
#define OUTD 64
#define E_TOT (NN*(KK+1))

// ---------------- scratch (device globals; no allocations allowed) ----------------
__device__ float g_xn[NN*DD];                       // normalized x
__device__ float g_adj[(size_t)NN*(size_t)NN];      // 604 MB similarity matrix
__device__ float g_topv[NN*KK];
__device__ int   g_topi[NN*KK];
__device__ float g_deg[NN];
__device__ float g_dis[NN];
__device__ int   g_cnt[NN];
__device__ int   g_off[NN+1];
__device__ int   g_fill[NN];
__device__ int   g_esrc[E_TOT];
__device__ float g_ew[E_TOT];
__device__ float g_hw1[NN*HID];
__device__ float g_h[NN*HID];
__device__ float g_hw2[NN*OUTD];

// ---------------- 1. row-normalize x ----------------
__global__ void normalize_kernel(const float* __restrict__ x) {
    int warp = (blockIdx.x * blockDim.x + threadIdx.x) >> 5;
    int lane = threadIdx.x & 31;
    if (warp >= NN) return;
    const float4* xr = (const float4*)(x + (size_t)warp * DD);
    float4 v = xr[lane];
    float ss = v.x*v.x + v.y*v.y + v.z*v.z + v.w*v.w;
    #pragma unroll
    for (int o = 16; o; o >>= 1) ss += __shfl_xor_sync(0xffffffffu, ss, o);
    float inv = 1.0f / fmaxf(sqrtf(ss), 1e-12f);
    float4 o4 = make_float4(v.x*inv, v.y*inv, v.z*inv, v.w*inv);
    ((float4*)(g_xn + (size_t)warp*DD))[lane] = o4;
}

// ---------------- 2. adj = xn @ xn^T, symmetric, fp32 SIMT GEMM ----------------
// 128x128 tile, 256 threads, 8x8 per thread, BK=8 double-buffered, LDS.128 reads.
// Only bx >= by blocks compute; bx > by also store the transposed mirror tile
// via a dedicated smem staging buffer (coalesced float4 writes both ways).
__global__ void __launch_bounds__(256) adj_gemm_kernel() {
    __shared__ __align__(16) float As[2][8][132];
    __shared__ __align__(16) float Bs[2][8][132];
    __shared__ __align__(16) float Tb[32][132];

    int bx = blockIdx.x, by = blockIdx.y;
    if (bx < by) return;

    int tid = threadIdx.x;
    int tx = tid & 15, ty = tid >> 4;
    int rowBase = by * 128, colBase = bx * 128;

    int lr = tid >> 1;                 // 0..127 (row within tile)
    int lq = (tid & 1) * 4;            // 0 or 4 (k sub-offset)
    const float* aptr = g_xn + (size_t)(rowBase + lr) * DD + lq;
    const float* bptr = g_xn + (size_t)(colBase + lr) * DD + lq;

    // prologue: fill buffer 0 (k 0..7)
    {
        float4 av = *(const float4*)aptr;
        float4 bv = *(const float4*)bptr;
        As[0][lq+0][lr]=av.x; As[0][lq+1][lr]=av.y; As[0][lq+2][lr]=av.z; As[0][lq+3][lr]=av.w;
        Bs[0][lq+0][lr]=bv.x; Bs[0][lq+1][lr]=bv.y; Bs[0][lq+2][lr]=bv.z; Bs[0][lq+3][lr]=bv.w;
    }
    __syncthreads();

    float acc[8][8];
    #pragma unroll
    for (int i = 0; i < 8; i++)
        #pragma unroll
        for (int j = 0; j < 8; j++) acc[i][j] = 0.f;

    int buf = 0;
    #pragma unroll 1
    for (int it = 0; it < 15; it++) {
        float4 anv = *(const float4*)(aptr + (it+1)*8);
        float4 bnv = *(const float4*)(bptr + (it+1)*8);
        #pragma unroll
        for (int k = 0; k < 8; k++) {
            float4 a0 = *(const float4*)&As[buf][k][ty*4];
            float4 a1 = *(const float4*)&As[buf][k][64+ty*4];
            float4 b0 = *(const float4*)&Bs[buf][k][tx*4];
            float4 b1 = *(const float4*)&Bs[buf][k][64+tx*4];
            float a[8] = {a0.x,a0.y,a0.z,a0.w,a1.x,a1.y,a1.z,a1.w};
            float b[8] = {b0.x,b0.y,b0.z,b0.w,b1.x,b1.y,b1.z,b1.w};
            #pragma unroll
            for (int i = 0; i < 8; i++)
                #pragma unroll
                for (int j = 0; j < 8; j++)
                    acc[i][j] += a[i] * b[j];
        }
        int nb = buf ^ 1;
        As[nb][lq+0][lr]=anv.x; As[nb][lq+1][lr]=anv.y; As[nb][lq+2][lr]=anv.z; As[nb][lq+3][lr]=anv.w;
        Bs[nb][lq+0][lr]=bnv.x; Bs[nb][lq+1][lr]=bnv.y; Bs[nb][lq+2][lr]=bnv.z; Bs[nb][lq+3][lr]=bnv.w;
        buf = nb;
        __syncthreads();
    }
    // final compute (buf == 1)
    #pragma unroll
    for (int k = 0; k < 8; k++) {
        float4 a0 = *(const float4*)&As[buf][k][ty*4];
        float4 a1 = *(const float4*)&As[buf][k][64+ty*4];
        float4 b0 = *(const float4*)&Bs[buf][k][tx*4];
        float4 b1 = *(const float4*)&Bs[buf][k][64+tx*4];
        float a[8] = {a0.x,a0.y,a0.z,a0.w,a1.x,a1.y,a1.z,a1.w};
        float b[8] = {b0.x,b0.y,b0.z,b0.w,b1.x,b1.y,b1.z,b1.w};
        #pragma unroll
        for (int i = 0; i < 8; i++)
            #pragma unroll
            for (int j = 0; j < 8; j++)
                acc[i][j] += a[i] * b[j];
    }

    // direct store: thread (tx,ty) owns rows {h*64 + ty*4 + i}, cols {jh*64 + tx*4 + j}
    #pragma unroll
    for (int i8 = 0; i8 < 8; i8++) {
        int row = rowBase + (i8 >> 2)*64 + ty*4 + (i8 & 3);
        #pragma unroll
        for (int jh = 0; jh < 2; jh++) {
            float4 v = make_float4(acc[i8][jh*4+0], acc[i8][jh*4+1],
                                   acc[i8][jh*4+2], acc[i8][jh*4+3]);
            *(float4*)&g_adj[(size_t)row * NN + colBase + jh*64 + tx*4] = v;
        }
    }

    // mirrored store for off-diagonal blocks: 4 chunks of 32 transposed columns.
    // Chunk cc covers tile cols [cc*32, cc*32+32): held by threads with
    // jh = cc>>1 and tx in [(cc&1)*8, (cc&1)*8+8).
    if (bx > by) {
        #pragma unroll 1
        for (int cc = 0; cc < 4; cc++) {
            if ((tx >> 3) == (cc & 1)) {
                int jh = cc >> 1;
                #pragma unroll
                for (int j = 0; j < 4; j++) {
                    int cl = (tx & 7)*4 + j;            // 0..31 local col
                    #pragma unroll
                    for (int i8 = 0; i8 < 8; i8++) {
                        int rl = (i8 >> 2)*64 + ty*4 + (i8 & 3);   // 0..127 local row
                        Tb[cl][rl] = acc[i8][jh*4 + j];
                    }
                }
            }
            __syncthreads();
            {
                int cl = tid >> 3;          // 0..31
                int f4 = tid & 7;           // 0..7
                #pragma unroll
                for (int m = 0; m < 4; m++) {
                    float4 v = *(const float4*)&Tb[cl][(f4 + 8*m)*4];
                    *(float4*)&g_adj[(size_t)(colBase + cc*32 + cl) * NN + rowBase + (f4 + 8*m)*4] = v;
                }
            }
            __syncthreads();
        }
    }
}

// ---------------- 3. per-row top-20 ----------------
__global__ void __launch_bounds__(128) topk_kernel() {
    int r = blockIdx.x;
    int tid = threadIdx.x;
    const float* row = g_adj + (size_t)r * NN;

    float lv[KK]; int li[KK];
    #pragma unroll
    for (int i = 0; i < KK; i++) { lv[i] = -2.f; li[i] = -1; }
    float vmin = -2.f; int pmin = 0;

    for (int c = tid*4; c < NN; c += 512) {
        float4 v4 = *(const float4*)(row + c);
        #pragma unroll
        for (int u = 0; u < 4; u++) {
            float v = (u==0)?v4.x:(u==1)?v4.y:(u==2)?v4.z:v4.w;
            if (v > vmin) {
                lv[pmin] = v; li[pmin] = c + u;
                vmin = lv[0]; pmin = 0;
                #pragma unroll
                for (int i = 1; i < KK; i++)
                    if (lv[i] < vmin) { vmin = lv[i]; pmin = i; }
            }
        }
    }

    __shared__ float sv[128*KK];
    __shared__ int   si[128*KK];
    __shared__ float rmax[128];
    __shared__ int   rpos[128];
    #pragma unroll
    for (int i = 0; i < KK; i++) { sv[tid*KK + i] = lv[i]; si[tid*KK + i] = li[i]; }
    __syncthreads();

    for (int sel = 0; sel < KK; sel++) {
        float mv = -3.f; int mp = 0;
        for (int j = tid; j < 128*KK; j += 128)
            if (sv[j] > mv) { mv = sv[j]; mp = j; }
        rmax[tid] = mv; rpos[tid] = mp;
        __syncthreads();
        for (int d = 64; d > 0; d >>= 1) {
            if (tid < d && rmax[tid + d] > rmax[tid]) {
                rmax[tid] = rmax[tid + d]; rpos[tid] = rpos[tid + d];
            }
            __syncthreads();
        }
        if (tid == 0) {
            int p = rpos[0];
            g_topv[r*KK + sel] = sv[p];
            g_topi[r*KK + sel] = si[p];
            sv[p] = -3.f;
        }
        __syncthreads();
    }
}

// ---------------- 4. init counters (re-zeroed every launch for determinism) ----------------
__global__ void init_kernel() {
    int i = blockIdx.x * blockDim.x + threadIdx.x;
    if (i < NN) { g_deg[i] = 0.f; g_cnt[i] = 0; }
}

// ---------------- 5. degree + in-count ----------------
__global__ void deg_kernel() {
    int r = blockIdx.x * blockDim.x + threadIdx.x;
    if (r >= NN) return;
    bool self = false;
    #pragma unroll
    for (int k = 0; k < KK; k++) {
        int c = g_topi[r*KK + k];
        float w = g_topv[r*KK + k];
        if (c == r) self = true;
        atomicAdd(&g_deg[c], w);
        atomicAdd(&g_cnt[c], 1);
    }
    atomicAdd(&g_deg[r], self ? 0.f : 1.f);
    atomicAdd(&g_cnt[r], 1);
}

// ---------------- 6. exclusive scan of cnt -> off (single block) ----------------
__global__ void __launch_bounds__(1024) scan_kernel() {
    __shared__ int partial[1024];
    int t = threadIdx.x;
    int base = t * 12;
    int local[12];
    int s = 0;
    #pragma unroll
    for (int i = 0; i < 12; i++) { local[i] = s; s += g_cnt[base + i]; }
    partial[t] = s;
    __syncthreads();
    for (int d = 1; d < 1024; d <<= 1) {
        int v = (t >= d) ? partial[t - d] : 0;
        __syncthreads();
        partial[t] += v;
        __syncthreads();
    }
    int chunk_off = (t == 0) ? 0 : partial[t - 1];
    #pragma unroll
    for (int i = 0; i < 12; i++) {
        int o = chunk_off + local[i];
        g_off[base + i] = o;
        g_fill[base + i] = o;
    }
    if (t == 1023) g_off[NN] = partial[1023];
}

// ---------------- 7. dis = deg>0 ? rsqrt(max(deg,1e-30)) : 0 ----------------
__global__ void dis_kernel() {
    int i = blockIdx.x * blockDim.x + threadIdx.x;
    if (i >= NN) return;
    float d = g_deg[i];
    g_dis[i] = (d > 0.f) ? (1.0f / sqrtf(fmaxf(d, 1e-30f))) : 0.f;
}

// ---------------- 8. build transposed CSR with normalized weights ----------------
__global__ void fill_kernel() {
    int r = blockIdx.x * blockDim.x + threadIdx.x;
    if (r >= NN) return;
    float dr = g_dis[r];
    bool self = false;
    #pragma unroll
    for (int k = 0; k < KK; k++) {
        int c = g_topi[r*KK + k];
        float w = g_topv[r*KK + k];
        if (c == r) self = true;
        int p = atomicAdd(&g_fill[c], 1);
        g_esrc[p] = r;
        g_ew[p] = dr * w * g_dis[c];
    }
    float lw = self ? 0.f : 1.f;
    int p = atomicAdd(&g_fill[r], 1);
    g_esrc[p] = r;
    g_ew[p] = dr * dr * lw;
}

// ---------------- 9. dense Y = X @ W  (scratch selected by template) ----------------
template <int DOUT, bool FIRST>
__global__ void xw_kernel(const float* __restrict__ xin, const float* __restrict__ W) {
    const float* X = FIRST ? xin : (const float*)g_h;
    float* Y = FIRST ? g_hw1 : g_hw2;
    __shared__ float xs[16][DD];
    int j = threadIdx.x;
    int r0 = blockIdx.x * 16;
    for (int idx = j; idx < 16 * DD; idx += DOUT)
        xs[idx >> 7][idx & 127] = X[(size_t)(r0 + (idx >> 7)) * DD + (idx & 127)];
    __syncthreads();
    float acc[16];
    #pragma unroll
    for (int i = 0; i < 16; i++) acc[i] = 0.f;
    for (int k = 0; k < DD; k++) {
        float w = W[k * DOUT + j];
        #pragma unroll
        for (int i = 0; i < 16; i++) acc[i] += xs[i][k] * w;
    }
    #pragma unroll
    for (int i = 0; i < 16; i++) Y[(size_t)(r0 + i) * DOUT + j] = acc[i];
}

// ---------------- 10. aggregate over in-edges (+bias, optional relu) ----------------
template <int DH, bool RELU>
__global__ void agg_kernel(const float* __restrict__ b, float* __restrict__ outp) {
    const float* hw = RELU ? g_hw1 : g_hw2;
    float* dst = RELU ? g_h : outp;
    int c = blockIdx.x;
    int t = threadIdx.x;
    int e0 = g_off[c], e1 = g_off[c + 1];
    float acc = b[t];
    for (int e = e0; e < e1; e++) {
        int s = g_esrc[e];
        float w = g_ew[e];
        acc += w * hw[(size_t)s * DH + t];
    }
    if (RELU) acc = fmaxf(acc, 0.f);
    dst[(size_t)c * DH + t] = acc;
}

// ---------------- launch ----------------
extern "C" void kernel_launch(void* const* d_in, const int* in_sizes, int n_in,
                              void* d_out, int out_size) {
    const float* x  = (const float*)d_in[0];
    const float* W1 = (const float*)d_in[1];
    const float* b1 = (const float*)d_in[2];
    const float* W2 = (const float*)d_in[3];
    const float* b2 = (const float*)d_in[4];
    float* out = (float*)d_out;

    init_kernel<<<(NN + 255)/256, 256>>>();
    normalize_kernel<<<NN/8, 256>>>(x);
    adj_gemm_kernel<<<dim3(NN/128, NN/128), 256>>>();
    topk_kernel<<<NN, 128>>>();
    deg_kernel<<<(NN + 255)/256, 256>>>();
    scan_kernel<<<1, 1024>>>();
    dis_kernel<<<(NN + 255)/256, 256>>>();
    fill_kernel<<<(NN + 255)/256, 256>>>();

    xw_kernel<HID, true><<<NN/16, HID>>>(x, W1);
    agg_kernel<HID, true><<<NN, HID>>>(b1, nullptr);
    xw_kernel<OUTD, false><<<NN/16, OUTD>>>(nullptr, W2);
    agg_kernel<OUTD, false><<<NN, OUTD>>>(b2, out);
    (void)in_sizes; (void)n_in; (void)out_size;
}

// round 7
// speedup vs baseline: 2.3346x; 2.1846x over previous
#include <cuda_runtime.h>
#include <math.h>
#include <stdint.h>

#define NN 12288
#define DD 128
#define KK 20
#define HID 128
#define OUTD 64
#define E_TOT (NN*(KK+1))
#define CAP 768
#define THRESH 0.18f
#define FB_BLOCKS 148

// ---------------- scratch (device globals; no allocations allowed) ----------------
__device__ float g_xn[NN*DD];
__device__ unsigned long long g_cand[(size_t)NN*CAP];   // packed (ordval<<32)|col
__device__ int   g_ccnt[NN];
__device__ int   g_fbcnt;
__device__ int   g_fblist[NN];
__device__ float g_fbrow[(size_t)FB_BLOCKS*NN];         // fallback row scratch (global, not smem)
__device__ float g_topv[NN*KK];
__device__ int   g_topi[NN*KK];
__device__ float g_deg[NN];
__device__ float g_dis[NN];
__device__ int   g_cnt[NN];
__device__ int   g_off[NN+1];
__device__ int   g_fill[NN];
__device__ int   g_esrc[E_TOT];
__device__ float g_ew[E_TOT];
__device__ float g_hw1[NN*HID];
__device__ float g_h[NN*HID];
__device__ float g_hw2[NN*OUTD];

// float <-> order-preserving u32 (full range incl. negatives)
__device__ __forceinline__ unsigned int ordmap(float f) {
    unsigned int b = __float_as_uint(f);
    return (b & 0x80000000u) ? ~b : (b | 0x80000000u);
}
__device__ __forceinline__ float ordunmap(unsigned int u) {
    unsigned int b = (u & 0x80000000u) ? (u ^ 0x80000000u) : ~u;
    return __uint_as_float(b);
}

// ---------------- 1. row-normalize x ----------------
__global__ void normalize_kernel(const float* __restrict__ x) {
    int warp = (blockIdx.x * blockDim.x + threadIdx.x) >> 5;
    int lane = threadIdx.x & 31;
    if (warp >= NN) return;
    const float4* xr = (const float4*)(x + (size_t)warp * DD);
    float4 v = xr[lane];
    float ss = v.x*v.x + v.y*v.y + v.z*v.z + v.w*v.w;
    #pragma unroll
    for (int o = 16; o; o >>= 1) ss += __shfl_xor_sync(0xffffffffu, ss, o);
    float inv = 1.0f / fmaxf(sqrtf(ss), 1e-12f);
    float4 o4 = make_float4(v.x*inv, v.y*inv, v.z*inv, v.w*inv);
    ((float4*)(g_xn + (size_t)warp*DD))[lane] = o4;
}

// ---------------- 2. init counters ----------------
__global__ void init_kernel() {
    int i = blockIdx.x * blockDim.x + threadIdx.x;
    if (i < NN) { g_deg[i] = 0.f; g_cnt[i] = 0; g_ccnt[i] = 0; }
    if (i == 0) g_fbcnt = 0;
}

// ---------------- 3. symmetric GEMM + threshold candidate extraction ----------------
__global__ void __launch_bounds__(256) gemm_cand_kernel() {
    __shared__ __align__(16) float As[2][8][132];
    __shared__ __align__(16) float Bs[2][8][132];

    int bx = blockIdx.x, by = blockIdx.y;
    if (bx < by) return;

    int tid = threadIdx.x;
    int tx = tid & 15, ty = tid >> 4;
    int rowBase = by * 128, colBase = bx * 128;

    int lr = tid >> 1;
    int lq = (tid & 1) * 4;
    const float* aptr = g_xn + (size_t)(rowBase + lr) * DD + lq;
    const float* bptr = g_xn + (size_t)(colBase + lr) * DD + lq;

    {
        float4 av = *(const float4*)aptr;
        float4 bv = *(const float4*)bptr;
        As[0][lq+0][lr]=av.x; As[0][lq+1][lr]=av.y; As[0][lq+2][lr]=av.z; As[0][lq+3][lr]=av.w;
        Bs[0][lq+0][lr]=bv.x; Bs[0][lq+1][lr]=bv.y; Bs[0][lq+2][lr]=bv.z; Bs[0][lq+3][lr]=bv.w;
    }
    __syncthreads();

    float acc[8][8];
    #pragma unroll
    for (int i = 0; i < 8; i++)
        #pragma unroll
        for (int j = 0; j < 8; j++) acc[i][j] = 0.f;

    int buf = 0;
    #pragma unroll 1
    for (int it = 0; it < 15; it++) {
        float4 anv = *(const float4*)(aptr + (it+1)*8);
        float4 bnv = *(const float4*)(bptr + (it+1)*8);
        #pragma unroll
        for (int k = 0; k < 8; k++) {
            float4 a0 = *(const float4*)&As[buf][k][ty*4];
            float4 a1 = *(const float4*)&As[buf][k][64+ty*4];
            float4 b0 = *(const float4*)&Bs[buf][k][tx*4];
            float4 b1 = *(const float4*)&Bs[buf][k][64+tx*4];
            float a[8] = {a0.x,a0.y,a0.z,a0.w,a1.x,a1.y,a1.z,a1.w};
            float b[8] = {b0.x,b0.y,b0.z,b0.w,b1.x,b1.y,b1.z,b1.w};
            #pragma unroll
            for (int i = 0; i < 8; i++)
                #pragma unroll
                for (int j = 0; j < 8; j++)
                    acc[i][j] += a[i] * b[j];
        }
        int nb = buf ^ 1;
        As[nb][lq+0][lr]=anv.x; As[nb][lq+1][lr]=anv.y; As[nb][lq+2][lr]=anv.z; As[nb][lq+3][lr]=anv.w;
        Bs[nb][lq+0][lr]=bnv.x; Bs[nb][lq+1][lr]=bnv.y; Bs[nb][lq+2][lr]=bnv.z; Bs[nb][lq+3][lr]=bnv.w;
        buf = nb;
        __syncthreads();
    }
    #pragma unroll
    for (int k = 0; k < 8; k++) {
        float4 a0 = *(const float4*)&As[buf][k][ty*4];
        float4 a1 = *(const float4*)&As[buf][k][64+ty*4];
        float4 b0 = *(const float4*)&Bs[buf][k][tx*4];
        float4 b1 = *(const float4*)&Bs[buf][k][64+tx*4];
        float a[8] = {a0.x,a0.y,a0.z,a0.w,a1.x,a1.y,a1.z,a1.w};
        float b[8] = {b0.x,b0.y,b0.z,b0.w,b1.x,b1.y,b1.z,b1.w};
        #pragma unroll
        for (int i = 0; i < 8; i++)
            #pragma unroll
            for (int j = 0; j < 8; j++)
                acc[i][j] += a[i] * b[j];
    }

    // epilogue: threshold filter + candidate append (no adj store)
    bool mirror = (bx > by);
    #pragma unroll
    for (int i8 = 0; i8 < 8; i8++) {
        int row = rowBase + (i8 >> 2)*64 + ty*4 + (i8 & 3);
        #pragma unroll
        for (int jh = 0; jh < 2; jh++) {
            #pragma unroll
            for (int jj = 0; jj < 4; jj++) {
                float v = acc[i8][jh*4 + jj];
                if (v > THRESH) {
                    int col = colBase + jh*64 + tx*4 + jj;
                    unsigned long long pk =
                        ((unsigned long long)ordmap(v) << 32) | (unsigned int)col;
                    int p = atomicAdd(&g_ccnt[row], 1);
                    if (p < CAP) g_cand[(size_t)row*CAP + p] = pk;
                    if (mirror) {
                        unsigned long long pk2 =
                            ((unsigned long long)ordmap(v) << 32) | (unsigned int)row;
                        int q = atomicAdd(&g_ccnt[col], 1);
                        if (q < CAP) g_cand[(size_t)col*CAP + q] = pk2;
                    }
                }
            }
        }
    }
}

// ---------------- 4. select top-20 from candidates (1 warp / row) ----------------
__global__ void __launch_bounds__(256) select_kernel() {
    int r = blockIdx.x * 8 + (threadIdx.x >> 5);
    int lane = threadIdx.x & 31;
    if (r >= NN) return;
    int c = g_ccnt[r];
    if (c < KK || c > CAP) {
        if (lane == 0) {
            int p = atomicAdd(&g_fbcnt, 1);
            g_fblist[p] = r;
        }
        return;
    }
    unsigned long long v[24];
    #pragma unroll
    for (int i = 0; i < 24; i++) {
        int idx = lane + i*32;
        v[i] = (idx < c) ? g_cand[(size_t)r*CAP + idx] : 0ULL;
    }
    unsigned int used = 0;
    for (int sel = 0; sel < KK; sel++) {
        unsigned long long best = 0ULL; int bi = -1;
        #pragma unroll
        for (int i = 0; i < 24; i++)
            if (!((used >> i) & 1u) && v[i] > best) { best = v[i]; bi = i; }
        int bl = lane;
        #pragma unroll
        for (int o = 16; o; o >>= 1) {
            unsigned long long ob = __shfl_xor_sync(0xffffffffu, best, o);
            int obl = __shfl_xor_sync(0xffffffffu, bl, o);
            if (ob > best) { best = ob; bl = obl; }
        }
        if (lane == bl) used |= (1u << bi);
        if (lane == 0) {
            g_topv[r*KK + sel] = ordunmap((unsigned int)(best >> 32));
            g_topi[r*KK + sel] = (int)(best & 0xFFFFFFFFu);
        }
    }
}

// ---------------- 5. fallback: exact recompute (global scratch, no big smem) ----------------
__global__ void __launch_bounds__(256) fallback_kernel() {
    __shared__ unsigned long long red[256];
    float* rowbuf = g_fbrow + (size_t)blockIdx.x * NN;
    int n = g_fbcnt;
    int t = threadIdx.x;
    for (int ii = blockIdx.x; ii < n; ii += gridDim.x) {
        int r = g_fblist[ii];
        const float* xr = g_xn + (size_t)r * DD;
        for (int col = t; col < NN; col += 256) {
            const float* xc = g_xn + (size_t)col * DD;
            float s = 0.f;
            #pragma unroll 16
            for (int k = 0; k < DD; k++) s += xr[k] * xc[k];
            rowbuf[col] = s;
        }
        __syncthreads();
        for (int sel = 0; sel < KK; sel++) {
            unsigned long long best = 0ULL;
            for (int col = t; col < NN; col += 256) {
                unsigned long long pk =
                    ((unsigned long long)ordmap(rowbuf[col]) << 32) | (unsigned int)col;
                if (pk > best) best = pk;
            }
            red[t] = best;
            __syncthreads();
            for (int d = 128; d > 0; d >>= 1) {
                if (t < d && red[t + d] > red[t]) red[t] = red[t + d];
                __syncthreads();
            }
            if (t == 0) {
                unsigned long long b = red[0];
                int bi = (int)(b & 0xFFFFFFFFu);
                g_topv[r*KK + sel] = ordunmap((unsigned int)(b >> 32));
                g_topi[r*KK + sel] = bi;
                rowbuf[bi] = -2.f;
            }
            __syncthreads();
        }
        __syncthreads();
    }
}

// ---------------- 6. degree + in-count ----------------
__global__ void deg_kernel() {
    int r = blockIdx.x * blockDim.x + threadIdx.x;
    if (r >= NN) return;
    bool self = false;
    #pragma unroll
    for (int k = 0; k < KK; k++) {
        int c = g_topi[r*KK + k];
        float w = g_topv[r*KK + k];
        if (c == r) self = true;
        atomicAdd(&g_deg[c], w);
        atomicAdd(&g_cnt[c], 1);
    }
    atomicAdd(&g_deg[r], self ? 0.f : 1.f);
    atomicAdd(&g_cnt[r], 1);
}

// ---------------- 7. exclusive scan of cnt -> off ----------------
__global__ void __launch_bounds__(1024) scan_kernel() {
    __shared__ int partial[1024];
    int t = threadIdx.x;
    int base = t * 12;
    int local[12];
    int s = 0;
    #pragma unroll
    for (int i = 0; i < 12; i++) { local[i] = s; s += g_cnt[base + i]; }
    partial[t] = s;
    __syncthreads();
    for (int d = 1; d < 1024; d <<= 1) {
        int v = (t >= d) ? partial[t - d] : 0;
        __syncthreads();
        partial[t] += v;
        __syncthreads();
    }
    int chunk_off = (t == 0) ? 0 : partial[t - 1];
    #pragma unroll
    for (int i = 0; i < 12; i++) {
        int o = chunk_off + local[i];
        g_off[base + i] = o;
        g_fill[base + i] = o;
    }
    if (t == 1023) g_off[NN] = partial[1023];
}

// ---------------- 8. dis ----------------
__global__ void dis_kernel() {
    int i = blockIdx.x * blockDim.x + threadIdx.x;
    if (i >= NN) return;
    float d = g_deg[i];
    g_dis[i] = (d > 0.f) ? (1.0f / sqrtf(fmaxf(d, 1e-30f))) : 0.f;
}

// ---------------- 9. build transposed CSR with normalized weights ----------------
__global__ void fill_kernel() {
    int r = blockIdx.x * blockDim.x + threadIdx.x;
    if (r >= NN) return;
    float dr = g_dis[r];
    bool self = false;
    #pragma unroll
    for (int k = 0; k < KK; k++) {
        int c = g_topi[r*KK + k];
        float w = g_topv[r*KK + k];
        if (c == r) self = true;
        int p = atomicAdd(&g_fill[c], 1);
        g_esrc[p] = r;
        g_ew[p] = dr * w * g_dis[c];
    }
    float lw = self ? 0.f : 1.f;
    int p = atomicAdd(&g_fill[r], 1);
    g_esrc[p] = r;
    g_ew[p] = dr * dr * lw;
}

// ---------------- 10. dense Y = X @ W ----------------
template <int DOUT, bool FIRST>
__global__ void xw_kernel(const float* __restrict__ xin, const float* __restrict__ W) {
    const float* X = FIRST ? xin : (const float*)g_h;
    float* Y = FIRST ? g_hw1 : g_hw2;
    __shared__ float xs[16][DD];
    int j = threadIdx.x;
    int r0 = blockIdx.x * 16;
    for (int idx = j; idx < 16 * DD; idx += DOUT)
        xs[idx >> 7][idx & 127] = X[(size_t)(r0 + (idx >> 7)) * DD + (idx & 127)];
    __syncthreads();
    float acc[16];
    #pragma unroll
    for (int i = 0; i < 16; i++) acc[i] = 0.f;
    for (int k = 0; k < DD; k++) {
        float w = W[k * DOUT + j];
        #pragma unroll
        for (int i = 0; i < 16; i++) acc[i] += xs[i][k] * w;
    }
    #pragma unroll
    for (int i = 0; i < 16; i++) Y[(size_t)(r0 + i) * DOUT + j] = acc[i];
}

// ---------------- 11. aggregate over in-edges ----------------
template <int DH, bool RELU>
__global__ void agg_kernel(const float* __restrict__ b, float* __restrict__ outp) {
    const float* hw = RELU ? g_hw1 : g_hw2;
    float* dst = RELU ? g_h : outp;
    int c = blockIdx.x;
    int t = threadIdx.x;
    int e0 = g_off[c], e1 = g_off[c + 1];
    float acc = b[t];
    for (int e = e0; e < e1; e++) {
        int s = g_esrc[e];
        float w = g_ew[e];
        acc += w * hw[(size_t)s * DH + t];
    }
    if (RELU) acc = fmaxf(acc, 0.f);
    dst[(size_t)c * DH + t] = acc;
}

// ---------------- launch ----------------
extern "C" void kernel_launch(void* const* d_in, const int* in_sizes, int n_in,
                              void* d_out, int out_size) {
    const float* x  = (const float*)d_in[0];
    const float* W1 = (const float*)d_in[1];
    const float* b1 = (const float*)d_in[2];
    const float* W2 = (const float*)d_in[3];
    const float* b2 = (const float*)d_in[4];
    float* out = (float*)d_out;

    init_kernel<<<(NN + 255)/256, 256>>>();
    normalize_kernel<<<NN/8, 256>>>(x);
    gemm_cand_kernel<<<dim3(NN/128, NN/128), 256>>>();
    select_kernel<<<NN/8, 256>>>();
    fallback_kernel<<<FB_BLOCKS, 256>>>();
    deg_kernel<<<(NN + 255)/256, 256>>>();
    scan_kernel<<<1, 1024>>>();
    dis_kernel<<<(NN + 255)/256, 256>>>();
    fill_kernel<<<(NN + 255)/256, 256>>>();

    xw_kernel<HID, true><<<NN/16, HID>>>(x, W1);
    agg_kernel<HID, true><<<NN, HID>>>(b1, nullptr);
    xw_kernel<OUTD, false><<<NN/16, OUTD>>>(nullptr, W2);
    agg_kernel<OUTD, false><<<NN, OUTD>>>(b2, out);
    (void)in_sizes; (void)n_in; (void)out_size;
}

// round 8
// speedup vs baseline: 2.6912x; 1.1528x over previous
#include <cuda_runtime.h>
#include <math.h>
#include <stdint.h>

#define NN 12288
#define DD 128
#define KK 20
#define HID 128
#define OUTD 64
#define E_TOT (NN*(KK+1))
#define CAP 768
#define THRESH 0.18f
#define FB_BLOCKS 148
#define NB 96                      // NN/128 tile count
#define TRI_BLOCKS (NB*(NB+1)/2)   // 4656

// ---------------- scratch (device globals; no allocations allowed) ----------------
__device__ float g_xn[NN*DD];
__device__ unsigned int g_cval[(size_t)NN*CAP];   // order-mapped values
__device__ unsigned int g_ccol[(size_t)NN*CAP];   // columns
__device__ int   g_ccnt[NN];
__device__ int   g_fbcnt;
__device__ int   g_fblist[NN];
__device__ float g_fbrow[(size_t)FB_BLOCKS*NN];
__device__ float g_topv[NN*KK];
__device__ int   g_topi[NN*KK];
__device__ float g_deg[NN];
__device__ float g_dis[NN];
__device__ int   g_cnt[NN];
__device__ int   g_off[NN+1];
__device__ int   g_fill[NN];
__device__ int   g_esrc[E_TOT];
__device__ float g_ew[E_TOT];
__device__ float g_hw1[NN*HID];
__device__ float g_h[NN*HID];
__device__ float g_hw2[NN*OUTD];

// float <-> order-preserving u32
__device__ __forceinline__ unsigned int ordmap(float f) {
    unsigned int b = __float_as_uint(f);
    return (b & 0x80000000u) ? ~b : (b | 0x80000000u);
}
__device__ __forceinline__ float ordunmap(unsigned int u) {
    unsigned int b = (u & 0x80000000u) ? (u ^ 0x80000000u) : ~u;
    return __uint_as_float(b);
}

// ---------------- 1. row-normalize x ----------------
__global__ void normalize_kernel(const float* __restrict__ x) {
    int warp = (blockIdx.x * blockDim.x + threadIdx.x) >> 5;
    int lane = threadIdx.x & 31;
    if (warp >= NN) return;
    const float4* xr = (const float4*)(x + (size_t)warp * DD);
    float4 v = xr[lane];
    float ss = v.x*v.x + v.y*v.y + v.z*v.z + v.w*v.w;
    #pragma unroll
    for (int o = 16; o; o >>= 1) ss += __shfl_xor_sync(0xffffffffu, ss, o);
    float inv = 1.0f / fmaxf(sqrtf(ss), 1e-12f);
    float4 o4 = make_float4(v.x*inv, v.y*inv, v.z*inv, v.w*inv);
    ((float4*)(g_xn + (size_t)warp*DD))[lane] = o4;
}

// ---------------- 2. init counters ----------------
__global__ void init_kernel() {
    int i = blockIdx.x * blockDim.x + threadIdx.x;
    if (i < NN) { g_deg[i] = 0.f; g_cnt[i] = 0; g_ccnt[i] = 0; }
    if (i == 0) g_fbcnt = 0;
}

// ---------------- 3. symmetric GEMM + threshold candidate extraction ----------------
// Triangular 1D grid: bid -> (by, bx) with bx >= by. 128x128 tile, 256 threads,
// 8x8/thread, BK=8 double-buffered, LDS.128 reads.
__global__ void __launch_bounds__(256) gemm_cand_kernel() {
    __shared__ __align__(16) float As[2][8][132];
    __shared__ __align__(16) float Bs[2][8][132];

    int bid = blockIdx.x;
    int by = (int)(96.5f - sqrtf(96.5f*96.5f - 2.0f*(float)bid));
    while (NB*by - by*(by-1)/2 > bid) by--;
    while (NB*(by+1) - (by+1)*by/2 <= bid) by++;
    int bx = by + bid - (NB*by - by*(by-1)/2);

    int tid = threadIdx.x;
    int tx = tid & 15, ty = tid >> 4;
    int rowBase = by * 128, colBase = bx * 128;

    int lr = tid >> 1;
    int lq = (tid & 1) * 4;
    const float* aptr = g_xn + (size_t)(rowBase + lr) * DD + lq;
    const float* bptr = g_xn + (size_t)(colBase + lr) * DD + lq;

    {
        float4 av = *(const float4*)aptr;
        float4 bv = *(const float4*)bptr;
        As[0][lq+0][lr]=av.x; As[0][lq+1][lr]=av.y; As[0][lq+2][lr]=av.z; As[0][lq+3][lr]=av.w;
        Bs[0][lq+0][lr]=bv.x; Bs[0][lq+1][lr]=bv.y; Bs[0][lq+2][lr]=bv.z; Bs[0][lq+3][lr]=bv.w;
    }
    __syncthreads();

    float acc[8][8];
    #pragma unroll
    for (int i = 0; i < 8; i++)
        #pragma unroll
        for (int j = 0; j < 8; j++) acc[i][j] = 0.f;

    int buf = 0;
    #pragma unroll 1
    for (int it = 0; it < 15; it++) {
        float4 anv = *(const float4*)(aptr + (it+1)*8);
        float4 bnv = *(const float4*)(bptr + (it+1)*8);
        #pragma unroll
        for (int k = 0; k < 8; k++) {
            float4 a0 = *(const float4*)&As[buf][k][ty*4];
            float4 a1 = *(const float4*)&As[buf][k][64+ty*4];
            float4 b0 = *(const float4*)&Bs[buf][k][tx*4];
            float4 b1 = *(const float4*)&Bs[buf][k][64+tx*4];
            float a[8] = {a0.x,a0.y,a0.z,a0.w,a1.x,a1.y,a1.z,a1.w};
            float b[8] = {b0.x,b0.y,b0.z,b0.w,b1.x,b1.y,b1.z,b1.w};
            #pragma unroll
            for (int i = 0; i < 8; i++)
                #pragma unroll
                for (int j = 0; j < 8; j++)
                    acc[i][j] += a[i] * b[j];
        }
        int nb = buf ^ 1;
        As[nb][lq+0][lr]=anv.x; As[nb][lq+1][lr]=anv.y; As[nb][lq+2][lr]=anv.z; As[nb][lq+3][lr]=anv.w;
        Bs[nb][lq+0][lr]=bnv.x; Bs[nb][lq+1][lr]=bnv.y; Bs[nb][lq+2][lr]=bnv.z; Bs[nb][lq+3][lr]=bnv.w;
        buf = nb;
        __syncthreads();
    }
    #pragma unroll
    for (int k = 0; k < 8; k++) {
        float4 a0 = *(const float4*)&As[buf][k][ty*4];
        float4 a1 = *(const float4*)&As[buf][k][64+ty*4];
        float4 b0 = *(const float4*)&Bs[buf][k][tx*4];
        float4 b1 = *(const float4*)&Bs[buf][k][64+tx*4];
        float a[8] = {a0.x,a0.y,a0.z,a0.w,a1.x,a1.y,a1.z,a1.w};
        float b[8] = {b0.x,b0.y,b0.z,b0.w,b1.x,b1.y,b1.z,b1.w};
        #pragma unroll
        for (int i = 0; i < 8; i++)
            #pragma unroll
            for (int j = 0; j < 8; j++)
                acc[i][j] += a[i] * b[j];
    }

    // epilogue: threshold filter + candidate append
    bool mirror = (bx > by);
    #pragma unroll
    for (int i8 = 0; i8 < 8; i8++) {
        int row = rowBase + (i8 >> 2)*64 + ty*4 + (i8 & 3);
        #pragma unroll
        for (int jh = 0; jh < 2; jh++) {
            #pragma unroll
            for (int jj = 0; jj < 4; jj++) {
                float v = acc[i8][jh*4 + jj];
                if (v > THRESH) {
                    int col = colBase + jh*64 + tx*4 + jj;
                    unsigned int ov = ordmap(v);
                    int p = atomicAdd(&g_ccnt[row], 1);
                    if (p < CAP) {
                        g_cval[(size_t)row*CAP + p] = ov;
                        g_ccol[(size_t)row*CAP + p] = (unsigned int)col;
                    }
                    if (mirror) {
                        int q = atomicAdd(&g_ccnt[col], 1);
                        if (q < CAP) {
                            g_cval[(size_t)col*CAP + q] = ov;
                            g_ccol[(size_t)col*CAP + q] = (unsigned int)row;
                        }
                    }
                }
            }
        }
    }
}

// ---------------- 4. select top-20 (1 warp / row, u32 path) ----------------
__global__ void __launch_bounds__(256) select_kernel() {
    int r = blockIdx.x * 8 + (threadIdx.x >> 5);
    int lane = threadIdx.x & 31;
    if (r >= NN) return;
    int c = g_ccnt[r];
    if (c < KK || c > CAP) {
        if (lane == 0) {
            int p = atomicAdd(&g_fbcnt, 1);
            g_fblist[p] = r;
        }
        return;
    }
    const unsigned int* src = g_cval + (size_t)r * CAP;
    unsigned int v[24];
    #pragma unroll
    for (int i = 0; i < 24; i++) {
        int idx = lane + i*32;
        v[i] = (idx < c) ? src[idx] : 0u;
    }
    // cached per-lane local max
    unsigned int m = 0;
    #pragma unroll
    for (int i = 0; i < 24; i++) m = max(m, v[i]);

    for (int sel = 0; sel < KK; sel++) {
        unsigned int wm = m;
        #pragma unroll
        for (int o = 16; o; o >>= 1)
            wm = max(wm, __shfl_xor_sync(0xffffffffu, wm, o));
        unsigned int ball = __ballot_sync(0xffffffffu, m == wm);
        int owner = __ffs(ball) - 1;
        if (lane == owner) {
            #pragma unroll
            for (int i = 0; i < 24; i++) {
                if (v[i] == wm) {
                    v[i] = 0u;
                    int idx = lane + i*32;
                    g_topv[r*KK + sel] = ordunmap(wm);
                    g_topi[r*KK + sel] = (int)g_ccol[(size_t)r*CAP + idx];
                    break;
                }
            }
            m = 0;
            #pragma unroll
            for (int i = 0; i < 24; i++) m = max(m, v[i]);
        }
    }
}

// ---------------- 5. fallback: exact recompute (global scratch) ----------------
__global__ void __launch_bounds__(256) fallback_kernel() {
    __shared__ unsigned long long red[256];
    float* rowbuf = g_fbrow + (size_t)blockIdx.x * NN;
    int n = g_fbcnt;
    int t = threadIdx.x;
    for (int ii = blockIdx.x; ii < n; ii += gridDim.x) {
        int r = g_fblist[ii];
        const float* xr = g_xn + (size_t)r * DD;
        for (int col = t; col < NN; col += 256) {
            const float* xc = g_xn + (size_t)col * DD;
            float s = 0.f;
            #pragma unroll 16
            for (int k = 0; k < DD; k++) s += xr[k] * xc[k];
            rowbuf[col] = s;
        }
        __syncthreads();
        for (int sel = 0; sel < KK; sel++) {
            unsigned long long best = 0ULL;
            for (int col = t; col < NN; col += 256) {
                unsigned long long pk =
                    ((unsigned long long)ordmap(rowbuf[col]) << 32) | (unsigned int)col;
                if (pk > best) best = pk;
            }
            red[t] = best;
            __syncthreads();
            for (int d = 128; d > 0; d >>= 1) {
                if (t < d && red[t + d] > red[t]) red[t] = red[t + d];
                __syncthreads();
            }
            if (t == 0) {
                unsigned long long b = red[0];
                int bi = (int)(b & 0xFFFFFFFFu);
                g_topv[r*KK + sel] = ordunmap((unsigned int)(b >> 32));
                g_topi[r*KK + sel] = bi;
                rowbuf[bi] = -2.f;
            }
            __syncthreads();
        }
        __syncthreads();
    }
}

// ---------------- 6. degree + in-count ----------------
__global__ void deg_kernel() {
    int r = blockIdx.x * blockDim.x + threadIdx.x;
    if (r >= NN) return;
    bool self = false;
    #pragma unroll
    for (int k = 0; k < KK; k++) {
        int c = g_topi[r*KK + k];
        float w = g_topv[r*KK + k];
        if (c == r) self = true;
        atomicAdd(&g_deg[c], w);
        atomicAdd(&g_cnt[c], 1);
    }
    atomicAdd(&g_deg[r], self ? 0.f : 1.f);
    atomicAdd(&g_cnt[r], 1);
}

// ---------------- 7. exclusive scan of cnt -> off ----------------
__global__ void __launch_bounds__(1024) scan_kernel() {
    __shared__ int partial[1024];
    int t = threadIdx.x;
    int base = t * 12;
    int local[12];
    int s = 0;
    #pragma unroll
    for (int i = 0; i < 12; i++) { local[i] = s; s += g_cnt[base + i]; }
    partial[t] = s;
    __syncthreads();
    for (int d = 1; d < 1024; d <<= 1) {
        int v = (t >= d) ? partial[t - d] : 0;
        __syncthreads();
        partial[t] += v;
        __syncthreads();
    }
    int chunk_off = (t == 0) ? 0 : partial[t - 1];
    #pragma unroll
    for (int i = 0; i < 12; i++) {
        int o = chunk_off + local[i];
        g_off[base + i] = o;
        g_fill[base + i] = o;
    }
    if (t == 1023) g_off[NN] = partial[1023];
}

// ---------------- 8. dis ----------------
__global__ void dis_kernel() {
    int i = blockIdx.x * blockDim.x + threadIdx.x;
    if (i >= NN) return;
    float d = g_deg[i];
    g_dis[i] = (d > 0.f) ? (1.0f / sqrtf(fmaxf(d, 1e-30f))) : 0.f;
}

// ---------------- 9. build transposed CSR with normalized weights ----------------
__global__ void fill_kernel() {
    int r = blockIdx.x * blockDim.x + threadIdx.x;
    if (r >= NN) return;
    float dr = g_dis[r];
    bool self = false;
    #pragma unroll
    for (int k = 0; k < KK; k++) {
        int c = g_topi[r*KK + k];
        float w = g_topv[r*KK + k];
        if (c == r) self = true;
        int p = atomicAdd(&g_fill[c], 1);
        g_esrc[p] = r;
        g_ew[p] = dr * w * g_dis[c];
    }
    float lw = self ? 0.f : 1.f;
    int p = atomicAdd(&g_fill[r], 1);
    g_esrc[p] = r;
    g_ew[p] = dr * dr * lw;
}

// ---------------- 10. dense Y = X @ W ----------------
template <int DOUT, bool FIRST>
__global__ void xw_kernel(const float* __restrict__ xin, const float* __restrict__ W) {
    const float* X = FIRST ? xin : (const float*)g_h;
    float* Y = FIRST ? g_hw1 : g_hw2;
    __shared__ float xs[16][DD];
    int j = threadIdx.x;
    int r0 = blockIdx.x * 16;
    for (int idx = j; idx < 16 * DD; idx += DOUT)
        xs[idx >> 7][idx & 127] = X[(size_t)(r0 + (idx >> 7)) * DD + (idx & 127)];
    __syncthreads();
    float acc[16];
    #pragma unroll
    for (int i = 0; i < 16; i++) acc[i] = 0.f;
    for (int k = 0; k < DD; k++) {
        float w = W[k * DOUT + j];
        #pragma unroll
        for (int i = 0; i < 16; i++) acc[i] += xs[i][k] * w;
    }
    #pragma unroll
    for (int i = 0; i < 16; i++) Y[(size_t)(r0 + i) * DOUT + j] = acc[i];
}

// ---------------- 11. aggregate over in-edges ----------------
template <int DH, bool RELU>
__global__ void agg_kernel(const float* __restrict__ b, float* __restrict__ outp) {
    const float* hw = RELU ? g_hw1 : g_hw2;
    float* dst = RELU ? g_h : outp;
    int c = blockIdx.x;
    int t = threadIdx.x;
    int e0 = g_off[c], e1 = g_off[c + 1];
    float acc = b[t];
    for (int e = e0; e < e1; e++) {
        int s = g_esrc[e];
        float w = g_ew[e];
        acc += w * hw[(size_t)s * DH + t];
    }
    if (RELU) acc = fmaxf(acc, 0.f);
    dst[(size_t)c * DH + t] = acc;
}

// ---------------- launch ----------------
extern "C" void kernel_launch(void* const* d_in, const int* in_sizes, int n_in,
                              void* d_out, int out_size) {
    const float* x  = (const float*)d_in[0];
    const float* W1 = (const float*)d_in[1];
    const float* b1 = (const float*)d_in[2];
    const float* W2 = (const float*)d_in[3];
    const float* b2 = (const float*)d_in[4];
    float* out = (float*)d_out;

    init_kernel<<<(NN + 255)/256, 256>>>();
    normalize_kernel<<<NN/8, 256>>>(x);
    gemm_cand_kernel<<<TRI_BLOCKS, 256>>>();
    select_kernel<<<NN/8, 256>>>();
    fallback_kernel<<<FB_BLOCKS, 256>>>();
    deg_kernel<<<(NN + 255)/256, 256>>>();
    scan_kernel<<<1, 1024>>>();
    dis_kernel<<<(NN + 255)/256, 256>>>();
    fill_kernel<<<(NN + 255)/256, 256>>>();

    xw_kernel<HID, true><<<NN/16, HID>>>(x, W1);
    agg_kernel<HID, true><<<NN, HID>>>(b1, nullptr);
    xw_kernel<OUTD, false><<<NN/16, OUTD>>>(nullptr, W2);
    agg_kernel<OUTD, false><<<NN, OUTD>>>(b2, out);
    (void)in_sizes; (void)n_in; (void)out_size;
}